// round 2
// baseline (speedup 1.0000x reference)
#include <cuda_runtime.h>
#include <cuda_fp16.h>
#include <cstdint>
#include <cstddef>

// ---------------------------------------------------------------------------
// TernaryLinear: out[8192,4096] = x[8192,4096] @ ternarize(W[4096,4096])^T
// sm_103 (no tcgen05 in this toolchain target) -> ldmatrix + mma.sync HMMA.
// fp64 mean(|W|) -> ternarize W to fp16 (exact) -> x to fp16 (rel err ~2.8e-4)
// -> fp16 HMMA GEMM with fp32 accumulation, 3-stage cp.async pipeline.
// ---------------------------------------------------------------------------

#define TOKENS 8192
#define KDIM   4096
#define NDIM   4096

__device__ __align__(16) __half g_Wt[(size_t)NDIM   * KDIM]; // ternary W fp16 [N,K]
__device__ __align__(16) __half g_Xh[(size_t)TOKENS * KDIM]; // x fp16 [M,K]
__device__ double g_partial[2048];
__device__ float  g_absmean;

// ======================= mean(|W|) reduction ==============================

__global__ void absmean_partial_k(const float* __restrict__ w) {
    __shared__ double sred[256];
    double acc = 0.0;
    size_t base = (size_t)blockIdx.x * 8192 + threadIdx.x;
#pragma unroll 8
    for (int i = 0; i < 32; i++) acc += (double)fabsf(w[base + (size_t)i * 256]);
    sred[threadIdx.x] = acc;
    __syncthreads();
    for (int s = 128; s > 0; s >>= 1) {
        if (threadIdx.x < s) sred[threadIdx.x] += sred[threadIdx.x + s];
        __syncthreads();
    }
    if (threadIdx.x == 0) g_partial[blockIdx.x] = sred[0];
}

__global__ void absmean_final_k() {
    __shared__ double sred[256];
    double acc = 0.0;
#pragma unroll
    for (int i = 0; i < 8; i++) acc += g_partial[threadIdx.x + i * 256];
    sred[threadIdx.x] = acc;
    __syncthreads();
    for (int s = 128; s > 0; s >>= 1) {
        if (threadIdx.x < s) sred[threadIdx.x] += sred[threadIdx.x + s];
        __syncthreads();
    }
    if (threadIdx.x == 0) g_absmean = (float)(sred[0] / 16777216.0);
}

// ======================= ternarize + convert ===============================

__global__ void ternarize_k(const float* __restrict__ w) {
    const float mean = g_absmean;
    size_t i = (size_t)blockIdx.x * blockDim.x + threadIdx.x;   // float4 index
    float4 v = reinterpret_cast<const float4*>(w)[i];
    float t0 = (fabsf(v.x) > mean) ? (v.x > 0.0f ? 1.0f : -1.0f) : 0.0f;
    float t1 = (fabsf(v.y) > mean) ? (v.y > 0.0f ? 1.0f : -1.0f) : 0.0f;
    float t2 = (fabsf(v.z) > mean) ? (v.z > 0.0f ? 1.0f : -1.0f) : 0.0f;
    float t3 = (fabsf(v.w) > mean) ? (v.w > 0.0f ? 1.0f : -1.0f) : 0.0f;
    reinterpret_cast<__half2*>(g_Wt)[2 * i]     = __floats2half2_rn(t0, t1);
    reinterpret_cast<__half2*>(g_Wt)[2 * i + 1] = __floats2half2_rn(t2, t3);
}

__global__ void xtohalf_k(const float* __restrict__ x) {
    size_t i = (size_t)blockIdx.x * blockDim.x + threadIdx.x;   // float4 index
    float4 v = reinterpret_cast<const float4*>(x)[i];
    reinterpret_cast<__half2*>(g_Xh)[2 * i]     = __floats2half2_rn(v.x, v.y);
    reinterpret_cast<__half2*>(g_Xh)[2 * i + 1] = __floats2half2_rn(v.z, v.w);
}

// ======================= HMMA GEMM =========================================
// CTA tile 128(M) x 128(N), K-tile 64 halves (128B swizzled rows).
// 8 warps: 4(M) x 2(N) grid, warp tile 32x64.
// 3-stage cp.async pipeline. fp32 accumulators in registers.

static constexpr int TM = 128;
static constexpr int TN = 128;
static constexpr int TKH = 64;                 // halves per K-tile
static constexpr int NIT = KDIM / TKH;         // 64
static constexpr int STAGES = 3;
static constexpr int ASTAGE = TM * TKH * 2;    // 16384
static constexpr int BSTAGE = TN * TKH * 2;    // 16384
static constexpr int STAGE_BYTES = ASTAGE + BSTAGE;       // 32768
static constexpr int SMEM_BYTES = STAGES * STAGE_BYTES;   // 98304

static __device__ __forceinline__ uint32_t smem_u32(const void* p) {
    uint32_t a;
    asm("{ .reg .u64 t; cvta.to.shared.u64 t, %1; cvt.u32.u64 %0, t; }"
        : "=r"(a) : "l"(p));
    return a;
}

static __device__ __forceinline__ void cp16(uint32_t dst, const void* src) {
    asm volatile("cp.async.cg.shared.global [%0], [%1], 16;"
                 :: "r"(dst), "l"((size_t)__cvta_generic_to_global(src)));
}
static __device__ __forceinline__ void cp_commit() {
    asm volatile("cp.async.commit_group;" ::: "memory");
}
template <int N>
static __device__ __forceinline__ void cp_wait() {
    asm volatile("cp.async.wait_group %0;" :: "n"(N) : "memory");
}

static __device__ __forceinline__ void ldsm4(uint32_t* r, uint32_t addr) {
    asm volatile("ldmatrix.sync.aligned.m8n8.x4.shared.b16 {%0,%1,%2,%3}, [%4];"
                 : "=r"(r[0]), "=r"(r[1]), "=r"(r[2]), "=r"(r[3])
                 : "r"(addr));
}

static __device__ __forceinline__ void mma16816(float* c, const uint32_t* a,
                                                uint32_t b0, uint32_t b1) {
    asm volatile(
        "mma.sync.aligned.m16n8k16.row.col.f32.f16.f16.f32 "
        "{%0,%1,%2,%3}, {%4,%5,%6,%7}, {%8,%9}, {%0,%1,%2,%3};"
        : "+f"(c[0]), "+f"(c[1]), "+f"(c[2]), "+f"(c[3])
        : "r"(a[0]), "r"(a[1]), "r"(a[2]), "r"(a[3]), "r"(b0), "r"(b1));
}

// swizzled store column: 16B chunk c16 (0..7) in row r -> byte col
static __device__ __forceinline__ uint32_t swz_col(int r, int c16) {
    return (uint32_t)((c16 * 16) ^ ((r & 7) << 4));
}

static __device__ __forceinline__ void load_chunk(int it, int stage, int tid,
                                                  int mBase, int nBase,
                                                  uint32_t sb) {
    const uint32_t base = sb + stage * STAGE_BYTES;
    const int kofs = it * TKH;
#pragma unroll
    for (int i = 0; i < 8; i++) {
        int u = tid + i * 256;              // 0..2047
        int v = u & 1023;
        int r = v >> 3, c16 = v & 7;
        uint32_t dst = base + (u >= 1024 ? ASTAGE : 0) + r * 128 + swz_col(r, c16);
        const __half* src = (u >= 1024)
            ? &g_Wt[(size_t)(nBase + r) * KDIM + kofs + c16 * 8]
            : &g_Xh[(size_t)(mBase + r) * KDIM + kofs + c16 * 8];
        cp16(dst, src);
    }
}

__global__ void __launch_bounds__(256, 2) gemm_k(float* __restrict__ out) {
    extern __shared__ char smem[];
    const uint32_t sb = smem_u32(smem);
    const int tid = threadIdx.x, wid = tid >> 5, lid = tid & 31;
    const int warpM = wid & 3;          // 0..3
    const int warpN = wid >> 2;         // 0..1
    const int mBase = blockIdx.y * TM;
    const int nBase = blockIdx.x * TN;

    float c[2][8][4];
#pragma unroll
    for (int tm = 0; tm < 2; tm++)
#pragma unroll
        for (int j = 0; j < 8; j++)
#pragma unroll
            for (int q = 0; q < 4; q++) c[tm][j][q] = 0.0f;

    // prologue: fill 2 stages
    load_chunk(0, 0, tid, mBase, nBase, sb); cp_commit();
    load_chunk(1, 1, tid, mBase, nBase, sb); cp_commit();

    const int lrow = lid & 15;          // row within 16-row ldmatrix group
    const int lcol = (lid >> 4) * 16;   // 0 or 16 bytes (k0-7 vs k8-15)

    for (int it = 0; it < NIT; it++) {
        cp_wait<STAGES - 2>();
        __syncthreads();
        if (it + STAGES - 1 < NIT)
            load_chunk(it + STAGES - 1, (it + STAGES - 1) % STAGES, tid,
                       mBase, nBase, sb);
        cp_commit();

        const uint32_t aB = sb + (it % STAGES) * STAGE_BYTES;
        const uint32_t bB = aB + ASTAGE;

#pragma unroll
        for (int ks = 0; ks < 4; ks++) {
            uint32_t a[2][4];
#pragma unroll
            for (int tm = 0; tm < 2; tm++) {
                int r = warpM * 32 + tm * 16 + lrow;
                uint32_t addr = aB + r * 128 +
                    (uint32_t)((ks * 32 + lcol) ^ ((r & 7) << 4));
                ldsm4(a[tm], addr);
            }
            uint32_t b[4][4];
#pragma unroll
            for (int g = 0; g < 4; g++) {
                int r = warpN * 64 + g * 16 + lrow;
                uint32_t addr = bB + r * 128 +
                    (uint32_t)((ks * 32 + lcol) ^ ((r & 7) << 4));
                ldsm4(b[g], addr);
            }
#pragma unroll
            for (int tm = 0; tm < 2; tm++)
#pragma unroll
                for (int j = 0; j < 8; j++) {
                    int g = j >> 1, s = j & 1;
                    mma16816(c[tm][j], a[tm], b[g][s], b[g][s + 2]);
                }
        }
    }

    // Epilogue: direct fp32 stores (float2 per accum pair)
#pragma unroll
    for (int tm = 0; tm < 2; tm++) {
#pragma unroll
        for (int j = 0; j < 8; j++) {
            int row = mBase + warpM * 32 + tm * 16 + (lid >> 2);
            int col = nBase + warpN * 64 + j * 8 + (lid & 3) * 2;
            float2* p0 = reinterpret_cast<float2*>(out + (size_t)row * NDIM + col);
            float2* p1 = reinterpret_cast<float2*>(out + (size_t)(row + 8) * NDIM + col);
            *p0 = make_float2(c[tm][j][0], c[tm][j][1]);
            *p1 = make_float2(c[tm][j][2], c[tm][j][3]);
        }
    }
}

// ======================= launch ============================================

extern "C" void kernel_launch(void* const* d_in, const int* in_sizes, int n_in,
                              void* d_out, int out_size) {
    const float* x = (const float*)d_in[0];
    const float* w = (const float*)d_in[1];
    float* out = (float*)d_out;

    cudaFuncSetAttribute(gemm_k, cudaFuncAttributeMaxDynamicSharedMemorySize,
                         SMEM_BYTES);

    absmean_partial_k<<<2048, 256>>>(w);
    absmean_final_k<<<1, 256>>>();
    ternarize_k<<<(NDIM * KDIM / 4) / 256, 256>>>(w);
    xtohalf_k<<<(TOKENS * KDIM / 4) / 256, 256>>>(x);
    gemm_k<<<dim3(NDIM / TN, TOKENS / TM), 256, SMEM_BYTES>>>(out);
}